// round 17
// baseline (speedup 1.0000x reference)
#include <cuda_runtime.h>
#include <cstdint>

#define T_STEPS 2048
#define BATCH   32
#define INDIM   512
#define HID     512
#define G4      2048   // 4*HID

typedef unsigned long long u64;

// packed f32x2 helpers
__device__ __forceinline__ u64 pk2(float x) {
    u64 r; asm("mov.b64 %0, {%1, %1};" : "=l"(r) : "f"(x)); return r;
}
__device__ __forceinline__ void ffma2(u64& d, u64 a, u64 b, u64 c) {
    asm("fma.rn.f32x2 %0, %1, %2, %3;" : "=l"(d) : "l"(a), "l"(b), "l"(c));
}
__device__ __forceinline__ void fadd2(u64& d, u64 a, u64 b) {
    asm("add.rn.f32x2 %0, %1, %2;" : "=l"(d) : "l"(a), "l"(b));
}
__device__ __forceinline__ float2 up2(u64 v) {
    float2 f; asm("mov.b64 {%0, %1}, %2;" : "=f"(f.x), "=f"(f.y) : "l"(v)); return f;
}
__device__ __forceinline__ float tanhfast(float x) {
    float r; asm("tanh.approx.f32 %0, %1;" : "=f"(r) : "f"(x)); return r;
}
__device__ __forceinline__ float sigfast(float x) {
    return fmaf(tanhfast(0.5f * x), 0.5f, 0.5f);
}

// -------- persistent device scratch --------
__device__ float    g_seqT[(size_t)T_STEPS * HID * BATCH]; // [t][k*32+b] (134MB)
__device__ float    g_hT[2][HID * BATCH];                  // h transposed [k*32+b]
__device__ unsigned g_bar2[2][32];                         // per-batch-group counters

// ============================================================================
// seq transpose: g_seqT[t][k*32+b] = seq[t][b][k]. 32x32 smem tile transpose.
// grid = T_STEPS*16 blocks (t, 32-k chunk), 256 threads.
// ============================================================================
__global__ void seqT_kernel(const float* __restrict__ seq) {
    __shared__ float tile[32][33];
    const int blk = blockIdx.x;
    const int t   = blk >> 4;
    const int kc  = blk & 15;
    const int tid = threadIdx.x;

    int b  = tid >> 3;
    int k4 = (tid & 7) * 4;
    float4 v = *(const float4*)(seq + ((size_t)t * 32 + b) * 512 + kc * 32 + k4);
    tile[b][k4 + 0] = v.x;
    tile[b][k4 + 1] = v.y;
    tile[b][k4 + 2] = v.z;
    tile[b][k4 + 3] = v.w;
    __syncthreads();

    int k  = tid >> 3;
    int b4 = (tid & 7) * 4;
    float4 w = make_float4(tile[b4 + 0][k], tile[b4 + 1][k],
                           tile[b4 + 2][k], tile[b4 + 3][k]);
    *(float4*)(g_seqT + (size_t)t * 16384 + (size_t)(kc * 32 + k) * 32 + b4) = w;
}

// ============================================================================
__global__ void reset_kernel() {
    if (threadIdx.x < 2) g_bar2[threadIdx.x][0] = 0u;
}

// ============================================================================
// 32r x 16b x (64k per warp) GEMM: whole warp walks k together.
//   wtile: [k][32] rows r=q*8+j (floats). Hs: [k][16] with b ^ (((k>>1)&1)<<3).
//   lane: tm = lane&3 (rows tm*8..+7), tn = lane>>2 (b pair tn*2).
//   Output partials into Red[(gid*16 + rpair)*17 + b] (u64 = 2 rows packed).
// ============================================================================
__device__ __forceinline__ void gemm32(
    const float* __restrict__ wtile, const float* __restrict__ Hs,
    u64* __restrict__ Red, int gid, int tm, int tn)
{
    u64 a[4][2];
    #pragma unroll
    for (int i = 0; i < 4; ++i) { a[i][0] = 0ull; a[i][1] = 0ull; }

    const float* wb  = wtile + gid * 64 * 32 + tm * 8;
    const float* hb0 = Hs + gid * 64 * 16 + (tn * 2);
    const float* hb1 = Hs + gid * 64 * 16 + ((tn * 2) ^ 8);

    #pragma unroll 4
    for (int k4 = 0; k4 < 16; ++k4) {
        #pragma unroll
        for (int s = 0; s < 4; ++s) {
            const int kk = k4 * 4 + s;
            ulonglong2 A0 = *(const ulonglong2*)(wb + kk * 32);
            ulonglong2 A1 = *(const ulonglong2*)(wb + kk * 32 + 4);
            const float* hp = (s >= 2) ? hb1 : hb0;   // ((kk>>1)&1) selects swizzle
            float2 hv = *(const float2*)(hp + kk * 16);
            u64 b0 = pk2(hv.x), b1 = pk2(hv.y);
            ffma2(a[0][0], A0.x, b0, a[0][0]);
            ffma2(a[0][1], A0.x, b1, a[0][1]);
            ffma2(a[1][0], A0.y, b0, a[1][0]);
            ffma2(a[1][1], A0.y, b1, a[1][1]);
            ffma2(a[2][0], A1.x, b0, a[2][0]);
            ffma2(a[2][1], A1.x, b1, a[2][1]);
            ffma2(a[3][0], A1.y, b0, a[3][0]);
            ffma2(a[3][1], A1.y, b1, a[3][1]);
        }
    }
    #pragma unroll
    for (int i = 0; i < 4; ++i) {
        Red[(gid * 16 + tm * 4 + i) * 17 + tn * 2    ] = a[i][0];
        Red[(gid * 16 + tm * 4 + i) * 17 + tn * 2 + 1] = a[i][1];
    }
}

// ============================================================================
// Fused persistent LSTM: 128 CTAs x 256 threads. CTA (jg,bg) owns hidden
// slice jb..jb+8 (32 gate rows) and batch half bb..bb+16. W_hh AND W_ih
// slices both SMEM-resident. Per step: h-GEMM -> cell -> arrive ->
// [xp(t+1) GEMM in the barrier-latency window] -> poll -> stage h(t+1).
// ============================================================================
__global__ __launch_bounds__(256) void lstm_fused_kernel(
    const float* __restrict__ h0,
    const float* __restrict__ c0,
    const float* __restrict__ Whh,
    const float* __restrict__ Wih,
    const float* __restrict__ bih,
    const float* __restrict__ bhh,
    float* __restrict__ out,
    long long out_size)
{
    extern __shared__ float sm[];
    float* Ws  = sm;                            // 512*32  [k][r]
    float* Wx  = Ws + 512 * 32;                 // 512*32  [k][r]
    float* Hs  = Wx + 512 * 32;                 // 512*16  [k][b^swz]
    u64*   Red = (u64*)(Hs + 512 * 16);         // 8*16*17
    float* Gs  = (float*)(Red + 8 * 16 * 17);   // 512  h-gates [r*16+b]
    float* Gx  = Gs + 512;                      // 2*512 xp gates (double buf)
    float* Bs  = Gx + 1024;                     // 32 bias
    float* Cs  = Bs + 32;                       // 128 c slice

    const int tid = threadIdx.x;
    const int ct  = blockIdx.x;
    const int jg  = ct >> 1;
    const int bg  = ct & 1;
    const int jb  = jg * 8;
    const int bb  = bg * 16;

    // ---- one-time: W_hh and W_ih slices -> [k][32] SMEM ----
    for (int idx = tid; idx < 32 * 512; idx += 256) {
        int r = idx & 31, k = idx >> 5;
        int q = r >> 3, j = r & 7;
        size_t row = (size_t)(q * 512 + jb + j) * 512 + k;
        Ws[k * 32 + r] = Whh[row];
        Wx[k * 32 + r] = Wih[row];
    }
    if (tid < 32) {
        int q = tid >> 3, j = tid & 7;
        Bs[tid] = bih[q * 512 + jb + j] + bhh[q * 512 + jb + j];
    }
    const int jj  = tid & 7;
    const int bbt = tid >> 3;                   // cell (j,b), tid<128
    if (tid < 128) Cs[bbt * 8 + jj] = c0[(bb + bbt) * 512 + jb + jj];
    __syncthreads();

    const int gid = tid >> 5;                   // warp = 64-k chunk
    const int lane = tid & 31;
    const int tm  = lane & 3;
    const int tn  = lane >> 2;

    // ---- prologue: xp(0) ----
    {   // stage seq[0] -> Hs (coalesced float4 from g_seqT)
        const float* ssrc = g_seqT;             // t = 0
        #pragma unroll
        for (int i = 0; i < 8; ++i) {
            int flat = tid + i * 256;
            int q  = flat & 3;
            int kr = flat >> 2;
            float4 v = *(const float4*)(ssrc + kr * 32 + bb + q * 4);
            *(float4*)(Hs + kr * 16 + ((q * 4) ^ (((kr >> 1) & 1) << 3))) = v;
        }
        __syncthreads();
        gemm32(Wx, Hs, Red, gid, tm, tn);
        __syncthreads();
        {
            int rp = tid >> 4, b = tid & 15;
            u64 s = Red[rp * 17 + b];
            #pragma unroll
            for (int g = 1; g < 8; ++g)
                fadd2(s, s, Red[(g * 16 + rp) * 17 + b]);
            float2 f = up2(s);
            Gx[(rp * 2    ) * 16 + b] = f.x + Bs[rp * 2];
            Gx[(rp * 2 + 1) * 16 + b] = f.y + Bs[rp * 2 + 1];
        }
        __syncthreads();
        // stage h0 -> Hs (scalar transpose, once)
        for (int idx = tid; idx < 512 * 16; idx += 256) {
            int b = idx & 15, k = idx >> 4;
            Hs[k * 16 + (b ^ (((k >> 1) & 1) << 3))] = h0[(bb + b) * 512 + k];
        }
        __syncthreads();
    }

    unsigned* const barp = &g_bar2[bg][0];
    const long long need = (long long)T_STEPS * BATCH * HID + 2LL * BATCH * HID;

    for (int t = 0; t < T_STEPS; ++t) {
        // ---- h GEMM ----
        gemm32(Ws, Hs, Red, gid, tm, tn);
        __syncthreads();
        {   // reduce 8 groups -> Gs
            int rp = tid >> 4, b = tid & 15;
            u64 s = Red[rp * 17 + b];
            #pragma unroll
            for (int g = 1; g < 8; ++g)
                fadd2(s, s, Red[(g * 16 + rp) * 17 + b]);
            float2 f = up2(s);
            Gs[(rp * 2    ) * 16 + b] = f.x;
            Gs[(rp * 2 + 1) * 16 + b] = f.y;
        }
        __syncthreads();

        // ---- cell update ----
        if (tid < 128) {
            const int j = jj, b = bbt;
            const float* Gxb = Gx + (t & 1) * 512;
            float zi = Gxb[(     j) * 16 + b] + Gs[(     j) * 16 + b];
            float zf = Gxb[( 8 + j) * 16 + b] + Gs[( 8 + j) * 16 + b];
            float zg = Gxb[(16 + j) * 16 + b] + Gs[(16 + j) * 16 + b];
            float zo = Gxb[(24 + j) * 16 + b] + Gs[(24 + j) * 16 + b];
            float ig = sigfast(zi);
            float fg = sigfast(zf);
            float gg = tanhfast(zg);
            float og = sigfast(zo);
            float cn = fg * Cs[b * 8 + j] + ig * gg;
            Cs[b * 8 + j] = cn;
            float hn = og * tanhfast(cn);

            g_hT[(t + 1) & 1][(jb + j) * 32 + bb + b] = hn;
            out[((size_t)t * 32 + bb + b) * 512 + jb + j] = hn;

            if (t == T_STEPS - 1 && out_size >= need) {
                size_t ob = (size_t)T_STEPS * BATCH * HID;
                out[ob + (bb + b) * 512 + jb + j]               = hn;
                out[ob + BATCH * HID + (bb + b) * 512 + jb + j] = cn;
            }
        }
        if (t == T_STEPS - 1) break;

        __threadfence();
        __syncthreads();
        if (tid == 0) atomicAdd(barp, 1u);      // arrive

        // ---- xp(t+1) in the barrier-latency window ----
        {
            const float* ssrc = g_seqT + (size_t)(t + 1) * 16384;
            #pragma unroll
            for (int i = 0; i < 8; ++i) {
                int flat = tid + i * 256;
                int q  = flat & 3;
                int kr = flat >> 2;
                float4 v = *(const float4*)(ssrc + kr * 32 + bb + q * 4);
                *(float4*)(Hs + kr * 16 + ((q * 4) ^ (((kr >> 1) & 1) << 3))) = v;
            }
            __syncthreads();
            gemm32(Wx, Hs, Red, gid, tm, tn);
            __syncthreads();
            int rp = tid >> 4, b = tid & 15;
            u64 s = Red[rp * 17 + b];
            #pragma unroll
            for (int g = 1; g < 8; ++g)
                fadd2(s, s, Red[(g * 16 + rp) * 17 + b]);
            float2 f = up2(s);
            float* Gxn = Gx + ((t + 1) & 1) * 512;
            Gxn[(rp * 2    ) * 16 + b] = f.x + Bs[rp * 2];
            Gxn[(rp * 2 + 1) * 16 + b] = f.y + Bs[rp * 2 + 1];
        }

        // ---- poll (latency mostly spent above), then stage h(t+1) ----
        if (tid == 0) {
            const unsigned target = (unsigned)(t + 1) * 64u;
            while (*((volatile unsigned*)barp) < target) { }
        }
        __syncthreads();
        {
            const float* hsrc = g_hT[(t + 1) & 1];
            #pragma unroll
            for (int i = 0; i < 8; ++i) {
                int flat = tid + i * 256;
                int q  = flat & 3;
                int kr = flat >> 2;
                float4 v = __ldcg((const float4*)(hsrc + kr * 32 + bb + q * 4));
                *(float4*)(Hs + kr * 16 + ((q * 4) ^ (((kr >> 1) & 1) << 3))) = v;
            }
            __syncthreads();
        }
    }
}

// ============================================================================
extern "C" void kernel_launch(void* const* d_in, const int* in_sizes, int n_in,
                              void* d_out, int out_size)
{
    const float* seq = (const float*)d_in[0];
    const float* h0  = (const float*)d_in[1];
    const float* c0  = (const float*)d_in[2];
    const float* Wih = (const float*)d_in[3];
    const float* Whh = (const float*)d_in[4];
    const float* bih = (const float*)d_in[5];
    const float* bhh = (const float*)d_in[6];
    float* out = (float*)d_out;
    (void)in_sizes; (void)n_in;

    reset_kernel<<<1, 32>>>();
    seqT_kernel<<<T_STEPS * 16, 256>>>(seq);

    size_t smem = (size_t)(512 * 32 + 512 * 32 + 512 * 16) * sizeof(float)  // Ws+Wx+Hs
                + (size_t)(8 * 16 * 17) * sizeof(u64)                       // Red
                + (size_t)(512 + 1024 + 32 + 128) * sizeof(float);          // Gs+Gx+Bs+Cs
    cudaFuncSetAttribute(lstm_fused_kernel,
                         cudaFuncAttributeMaxDynamicSharedMemorySize, (int)smem);
    lstm_fused_kernel<<<128, 256, smem>>>(h0, c0, Whh, Wih, bih, bhh,
                                          out, (long long)out_size);
}